// round 13
// baseline (speedup 1.0000x reference)
#include <cuda_runtime.h>
#include <math.h>
#include <float.h>

// Problem constants
#define NROWS   16384        // 8*2048
#define DIM     64
#define NEMB    8192
#define TOPK    10
#define SPLITK  8
#define CPART   (NEMB / SPLITK)   // 1024 candidates per part
#define TC_TILE 64                // candidates per e-tile
#define NTILE   (CPART / TC_TILE) // 16
#define RPB     64                // rows per block
#define RSTRIDE 272               // padded row stride in shared (bytes)

// Output layout (float32 concat of tuple in return order)
#define OFF_Q     0
#define OFF_LOSS  (NROWS * DIM)                 // 1048576
#define OFF_IDX   (OFF_LOSS + 1)                // 1048577
#define OFF_MIND  (OFF_IDX + NROWS)             // 1064961
#define OFF_PERP  (OFF_MIND + NROWS)            // 1081345

typedef unsigned long long ull;

// ---- packed fp32x2 helpers (PTX only; ptxas won't auto-fuse) ----
__device__ __forceinline__ ull fma2(ull a, ull b, ull c) {
    ull d;
    asm("fma.rn.f32x2 %0, %1, %2, %3;" : "=l"(d) : "l"(a), "l"(b), "l"(c));
    return d;
}
__device__ __forceinline__ float lo2(ull a) { return __uint_as_float((unsigned)a); }
__device__ __forceinline__ float hi2(ull a) { return __uint_as_float((unsigned)(a >> 32)); }

// ---- scratch (static device arrays: no allocation allowed) ----
__device__ float g_topd[NROWS * SPLITK * TOPK];
__device__ int   g_topi[NROWS * SPLITK * TOPK];
__device__ float g_enorm[NEMB];
__device__ float g_xn[NROWS];
__device__ int   g_counts[NEMB];
__device__ float g_rowloss[NROWS];
__device__ int   g_selbi[NROWS];
__device__ int   g_selv[NROWS];

// ============================================================
// Phase 0: codebook norms + zero counts + input row norms
// ============================================================
__global__ void k_prep(const float* __restrict__ cb, const float* __restrict__ inputs) {
    int i = blockIdx.x * blockDim.x + threadIdx.x;
    if (i < NEMB) {
        const float4* r = reinterpret_cast<const float4*>(cb + (size_t)i * DIM);
        float s = 0.f;
#pragma unroll
        for (int j = 0; j < DIM / 4; j++) {
            float4 v = r[j];
            s += v.x * v.x + v.y * v.y + v.z * v.z + v.w * v.w;
        }
        g_enorm[i] = s;
        g_counts[i] = 0;
    } else if (i < NEMB + NROWS) {
        int row = i - NEMB;
        const float4* r = reinterpret_cast<const float4*>(inputs + (size_t)row * DIM);
        float s = 0.f;
#pragma unroll
        for (int j = 0; j < DIM / 4; j++) {
            float4 v = r[j];
            s += v.x * v.x + v.y * v.y + v.z * v.z + v.w * v.w;
        }
        g_xn[row] = s;
    }
}

// ---- top-10 sorted insert (strict <: stable for index ties) ----
#define INSERT10(TD, TI, DIST, CIDX)                                          \
    if ((DIST) < TD[9]) {                                                     \
        TD[9] = (DIST); TI[9] = (CIDX);                                       \
        _Pragma("unroll")                                                     \
        for (int _q = 9; _q > 0; --_q) {                                      \
            if (TD[_q] < TD[_q - 1]) {                                        \
                float _tf = TD[_q]; TD[_q] = TD[_q - 1]; TD[_q - 1] = _tf;    \
                int _ti = TI[_q]; TI[_q] = TI[_q - 1]; TI[_q - 1] = _ti;      \
            }                                                                 \
        }                                                                     \
    }

// ============================================================
// Phase 1: distances + per-(row, part) top-10
// grid = SPLITK * 256 blocks, 256 threads.
// Thread tile: 2 rows x 8 candidates. x-tile (64 rows) and
// e-tile (64 cands) both in shared -> LDS:fma2 = 10:32 (vs 16:32
// in the row-in-registers design), relieving the 1-wavefront/cyc
// smem crossbar that bound the previous kernel.
// e-tile xor-swizzled (chunk ^ tc) -> conflict-free 8-address loads.
// ============================================================
__global__ void __launch_bounds__(256, 2)
k_dist(const float* __restrict__ inputs, const float* __restrict__ cb) {
    __shared__ __align__(16) unsigned char sh[RPB * RSTRIDE * 2 + TC_TILE * 4];
    unsigned char* shx = sh;                          // 64 rows  * 272B
    unsigned char* she = sh + RPB * RSTRIDE;          // 64 cands * 272B
    float* shen = (float*)(sh + 2 * RPB * RSTRIDE);   // 64 norms

    const int part = blockIdx.x >> 8;    // 0..7
    const int rb   = blockIdx.x & 255;   // 0..255
    const int tid  = threadIdx.x;
    const int tr   = tid >> 3;           // 0..31 (row pair)
    const int tc   = tid & 7;            // 0..7  (cand group)
    const int row0 = rb * RPB + 2 * tr;

    // ---- load x tile: 64 rows x 16 chunks of 16B, unswizzled ----
#pragma unroll
    for (int k = 0; k < 4; k++) {
        int idx = tid + k * 256;
        int r = idx >> 4, ch = idx & 15;
        float4 v = reinterpret_cast<const float4*>(inputs + (size_t)(rb * RPB + r) * DIM)[ch];
        *reinterpret_cast<float4*>(shx + r * RSTRIDE + ch * 16) = v;
    }
    const float xn0 = g_xn[row0];
    const float xn1 = g_xn[row0 + 1];

    float td0[TOPK], td1[TOPK];
    int   ti0[TOPK], ti1[TOPK];
#pragma unroll
    for (int j = 0; j < TOPK; j++) {
        td0[j] = FLT_MAX; ti0[j] = 0x7fffffff;
        td1[j] = FLT_MAX; ti1[j] = 0x7fffffff;
    }

    const int cbase0 = part * CPART;
    const unsigned char* px0 = shx + (2 * tr) * RSTRIDE;
    const unsigned char* px1 = px0 + RSTRIDE;
    const unsigned char* pe  = she + (tc * 8) * RSTRIDE;  // this thread's first cand row

    for (int t = 0; t < NTILE; t++) {
        const int cb0 = cbase0 + t * TC_TILE;
        __syncthreads();
        // ---- load e tile: 64 cands x 16 chunks, xor-swizzled by (c>>3)&7 ----
#pragma unroll
        for (int k = 0; k < 4; k++) {
            int idx = tid + k * 256;
            int c = idx >> 4, ch = idx & 15;
            float4 v = reinterpret_cast<const float4*>(cb + (size_t)(cb0 + c) * DIM)[ch];
            *reinterpret_cast<float4*>(she + c * RSTRIDE + ((ch ^ ((c >> 3) & 7)) * 16)) = v;
        }
        if (tid < TC_TILE) shen[tid] = g_enorm[cb0 + tid];
        __syncthreads();

        // ---- 2x8 register tile over 64 dims ----
        ull a00 = 0, a01 = 0, a02 = 0, a03 = 0, a04 = 0, a05 = 0, a06 = 0, a07 = 0;
        ull a10 = 0, a11 = 0, a12 = 0, a13 = 0, a14 = 0, a15 = 0, a16 = 0, a17 = 0;
#pragma unroll
        for (int d = 0; d < 16; d++) {
            ulonglong2 xa = *reinterpret_cast<const ulonglong2*>(px0 + d * 16);
            ulonglong2 xb = *reinterpret_cast<const ulonglong2*>(px1 + d * 16);
            const unsigned char* ped = pe + ((d ^ tc) * 16);
            // half 1: cands j=0..3
            ulonglong2 e0 = *reinterpret_cast<const ulonglong2*>(ped);
            ulonglong2 e1 = *reinterpret_cast<const ulonglong2*>(ped + RSTRIDE);
            ulonglong2 e2 = *reinterpret_cast<const ulonglong2*>(ped + 2 * RSTRIDE);
            ulonglong2 e3 = *reinterpret_cast<const ulonglong2*>(ped + 3 * RSTRIDE);
            a00 = fma2(xa.x, e0.x, a00);
            a01 = fma2(xa.x, e1.x, a01);
            a02 = fma2(xa.x, e2.x, a02);
            a03 = fma2(xa.x, e3.x, a03);
            a10 = fma2(xb.x, e0.x, a10);
            a11 = fma2(xb.x, e1.x, a11);
            a12 = fma2(xb.x, e2.x, a12);
            a13 = fma2(xb.x, e3.x, a13);
            a00 = fma2(xa.y, e0.y, a00);
            a01 = fma2(xa.y, e1.y, a01);
            a02 = fma2(xa.y, e2.y, a02);
            a03 = fma2(xa.y, e3.y, a03);
            a10 = fma2(xb.y, e0.y, a10);
            a11 = fma2(xb.y, e1.y, a11);
            a12 = fma2(xb.y, e2.y, a12);
            a13 = fma2(xb.y, e3.y, a13);
            // half 2: cands j=4..7
            ulonglong2 e4 = *reinterpret_cast<const ulonglong2*>(ped + 4 * RSTRIDE);
            ulonglong2 e5 = *reinterpret_cast<const ulonglong2*>(ped + 5 * RSTRIDE);
            ulonglong2 e6 = *reinterpret_cast<const ulonglong2*>(ped + 6 * RSTRIDE);
            ulonglong2 e7 = *reinterpret_cast<const ulonglong2*>(ped + 7 * RSTRIDE);
            a04 = fma2(xa.x, e4.x, a04);
            a05 = fma2(xa.x, e5.x, a05);
            a06 = fma2(xa.x, e6.x, a06);
            a07 = fma2(xa.x, e7.x, a07);
            a14 = fma2(xb.x, e4.x, a14);
            a15 = fma2(xb.x, e5.x, a15);
            a16 = fma2(xb.x, e6.x, a16);
            a17 = fma2(xb.x, e7.x, a17);
            a04 = fma2(xa.y, e4.y, a04);
            a05 = fma2(xa.y, e5.y, a05);
            a06 = fma2(xa.y, e6.y, a06);
            a07 = fma2(xa.y, e7.y, a07);
            a14 = fma2(xb.y, e4.y, a14);
            a15 = fma2(xb.y, e5.y, a15);
            a16 = fma2(xb.y, e6.y, a16);
            a17 = fma2(xb.y, e7.y, a17);
        }

        // ---- epilogue: 16 distances, insert into per-row top-10 ----
        const int cloc = cb0 + tc * 8;
#define EPI(J, A0, A1)                                                        \
        {                                                                     \
            float en = shen[tc * 8 + (J)];                                    \
            float dot0 = lo2(A0) + hi2(A0);                                   \
            float dist0 = fmaf(-2.f, dot0, xn0 + en);                         \
            INSERT10(td0, ti0, dist0, cloc + (J));                            \
            float dot1 = lo2(A1) + hi2(A1);                                   \
            float dist1 = fmaf(-2.f, dot1, xn1 + en);                         \
            INSERT10(td1, ti1, dist1, cloc + (J));                            \
        }
        EPI(0, a00, a10) EPI(1, a01, a11) EPI(2, a02, a12) EPI(3, a03, a13)
        EPI(4, a04, a14) EPI(5, a05, a15) EPI(6, a06, a16) EPI(7, a07, a17)
#undef EPI
    }

    // ---- 8-way warp-shuffle merge per row (lanes tc=0..7 hold disjoint
    //      candidate subsets; lexicographic (d, idx) min = JAX tie order) ----
#define MERGE_ROW(TD, TI, ROW)                                                \
    {                                                                         \
        float ld[TOPK]; int li[TOPK];                                         \
        _Pragma("unroll")                                                     \
        for (int s = 0; s < TOPK; s++) { ld[s] = TD[s]; li[s] = TI[s]; }      \
        float md[TOPK]; int mi[TOPK];                                         \
        _Pragma("unroll")                                                     \
        for (int s = 0; s < TOPK; s++) {                                      \
            float pd = ld[0]; int pi = li[0];                                 \
            _Pragma("unroll")                                                 \
            for (int m = 1; m <= 4; m <<= 1) {                                \
                float od = __shfl_xor_sync(0xffffffffu, pd, m, 8);            \
                int   oi = __shfl_xor_sync(0xffffffffu, pi, m, 8);            \
                if (od < pd || (od == pd && oi < pi)) { pd = od; pi = oi; }   \
            }                                                                 \
            md[s] = pd; mi[s] = pi;                                           \
            if (li[0] == pi && ld[0] == pd) {                                 \
                _Pragma("unroll")                                             \
                for (int q = 0; q < TOPK - 1; q++) { ld[q] = ld[q+1]; li[q] = li[q+1]; } \
                ld[TOPK - 1] = FLT_MAX; li[TOPK - 1] = 0x7fffffff;            \
            }                                                                 \
        }                                                                     \
        if (tc == 0) {                                                        \
            int o = ((ROW) * SPLITK + part) * TOPK;                           \
            _Pragma("unroll")                                                 \
            for (int s = 0; s < TOPK; s++) { g_topd[o + s] = md[s]; g_topi[o + s] = mi[s]; } \
        }                                                                     \
    }
    MERGE_ROW(td0, ti0, row0)
    MERGE_ROW(td1, ti1, row0 + 1)
#undef MERGE_ROW
}

// ============================================================
// Phase 2a: 8-way stable merge across parts -> Gumbel-max select
// ============================================================
__global__ void k_select(const float* __restrict__ gumbel,
                         float* __restrict__ out) {
    int row = blockIdx.x * blockDim.x + threadIdx.x;
    if (row >= NROWS) return;

    const float* td = g_topd + (size_t)row * SPLITK * TOPK;
    const int*   ti = g_topi + (size_t)row * SPLITK * TOPK;

    int pos[SPLITK];
#pragma unroll
    for (int p = 0; p < SPLITK; p++) pos[p] = 0;

    float bests = -FLT_MAX;
    int   bi = 0;
    float bd = 0.f;

#pragma unroll
    for (int s = 0; s < TOPK; s++) {
        float md = FLT_MAX;
        int mp = 0, mpos = 0;
#pragma unroll
        for (int p = 0; p < SPLITK; p++) {
            int pp = pos[p];
            float v = (pp < TOPK) ? td[p * TOPK + pp] : FLT_MAX;
            if (v < md) { md = v; mp = p; mpos = pp; }  // strict: ties -> lower part = lower idx
        }
        int id = ti[mp * TOPK + mpos];
#pragma unroll
        for (int p = 0; p < SPLITK; p++) if (p == mp) pos[p]++;

        float sc = gumbel[row * TOPK + s] - md;   // logits = -d/TEMP, TEMP=1
        if (sc > bests) { bests = sc; bi = id; bd = md; }  // strict: argmax first-index
    }

    bool valid = g_xn[row] > 1e-12f;   // ||x|| > 1e-6

    out[OFF_IDX + row]  = (float)(valid ? bi : 0);
    out[OFF_MIND + row] = valid ? bd : 0.f;
    g_selbi[row] = bi;
    g_selv[row]  = valid ? 1 : 0;
    if (valid) atomicAdd(&g_counts[bi], 1);   // integer atomics: deterministic
}

// ============================================================
// Phase 2b: coalesced gather + quantized_st + per-row loss
// ============================================================
__global__ void k_gather(const float* __restrict__ inputs,
                         const float* __restrict__ cb,
                         float* __restrict__ out) {
    const int t    = blockIdx.x * blockDim.x + threadIdx.x;
    const int row  = t >> 4;
    const int lane = t & 15;

    const int bi    = g_selbi[row];
    const int valid = g_selv[row];

    float4 xv = reinterpret_cast<const float4*>(inputs + (size_t)row * DIM)[lane];
    float4 qv = make_float4(0.f, 0.f, 0.f, 0.f);
    if (valid) qv = reinterpret_cast<const float4*>(cb + (size_t)bi * DIM)[lane];

    float4 st;
    float dx = qv.x - xv.x, dy = qv.y - xv.y, dz = qv.z - xv.z, dw = qv.w - xv.w;
    st.x = xv.x + dx; st.y = xv.y + dy; st.z = xv.z + dz; st.w = xv.w + dw;
    reinterpret_cast<float4*>(out + OFF_Q + (size_t)row * DIM)[lane] = st;

    float lsum = valid ? (dx * dx + dy * dy + dz * dz + dw * dw) : 0.f;
#pragma unroll
    for (int o = 8; o > 0; o >>= 1)
        lsum += __shfl_down_sync(0xffffffffu, lsum, o, 16);
    if (lane == 0) g_rowloss[row] = lsum;
}

// ============================================================
// Phase 3: deterministic reductions -> total_loss, perplexity
// ============================================================
__global__ void k_finalize(float* __restrict__ out) {
    __shared__ float sf[1024];
    const int t = threadIdx.x;

    int cs = 0;
    for (int i = t; i < NEMB; i += 1024) cs += g_counts[i];
    sf[t] = (float)cs;
    __syncthreads();
    for (int s = 512; s > 0; s >>= 1) { if (t < s) sf[t] += sf[t + s]; __syncthreads(); }
    float nv = fmaxf(sf[0], 1.0f);
    __syncthreads();

    float es = 0.f;
    for (int i = t; i < NEMB; i += 1024) {
        float p = (float)g_counts[i] / nv;
        es += p * logf(p + 1e-10f);
    }
    sf[t] = es;
    __syncthreads();
    for (int s = 512; s > 0; s >>= 1) { if (t < s) sf[t] += sf[t + s]; __syncthreads(); }
    float S = sf[0];
    __syncthreads();

    float ls = 0.f;
    for (int i = t; i < NROWS; i += 1024) ls += g_rowloss[i];
    sf[t] = ls;
    __syncthreads();
    for (int s = 512; s > 0; s >>= 1) { if (t < s) sf[t] += sf[t + s]; __syncthreads(); }

    if (t == 0) {
        float loss_vq = sf[0] / (nv * (float)DIM);
        float perp    = expf(-S);
        float ploss   = -logf(perp + 1e-10f);
        out[OFF_LOSS] = loss_vq + 0.01f * ploss;
        out[OFF_PERP] = perp;
    }
}

// ============================================================
extern "C" void kernel_launch(void* const* d_in, const int* in_sizes, int n_in,
                              void* d_out, int out_size) {
    const float* inputs = nullptr;
    const float* codebook = nullptr;
    const float* gumbel = nullptr;
    for (int i = 0; i < n_in; i++) {
        int s = in_sizes[i];
        if (s == NROWS * DIM)       inputs   = (const float*)d_in[i];
        else if (s == NEMB * DIM)   codebook = (const float*)d_in[i];
        else if (s == NROWS * TOPK) gumbel   = (const float*)d_in[i];
    }
    float* out = (float*)d_out;

    k_prep<<<(NEMB + NROWS + 255) / 256, 256>>>(codebook, inputs);
    k_dist<<<SPLITK * 256, 256>>>(inputs, codebook);
    k_select<<<NROWS / 256, 256>>>(gumbel, out);
    k_gather<<<(NROWS * 16) / 256, 256>>>(inputs, codebook, out);
    k_finalize<<<1, 1024>>>(out);
}